// round 15
// baseline (speedup 1.0000x reference)
#include <cuda_runtime.h>
#include <cuda_fp16.h>
#include <math.h>
#include <stdint.h>

#define KPOLY 20000
#define PMAX 30
#define NUM_PTS 5
#define C1 112
#define C2 224
#define PE_DIM 32
#define GEO_DIM 256
#define ROWS_TOTAL (KPOLY * NUM_PTS)   // 100000
#define TILE_M 64
#define GRID_C ((ROWS_TOTAL + TILE_M - 1) / TILE_M)   // 1563
#define KSTEPS 7

// B fragment-ordered global: [kk][jgrp=28][ks=7][lane=32][8B] -> 50176 B per kk
#define BKK_BYTES 50176
__device__ __half g_bf[3 * BKK_BYTES / 2];

// static SMEM layout (bytes); ~25.8 KB -> occ limited by regs (2 CTAs)
#define SAB_A 288                         // A row stride (LDS.64 conflict-free)
#define SM_BGB  0                         // 672 floats -> 2688
#define SM_SC   2688                      // 140 floats -> 3248
#define SM_W1   3264                      // 672 floats -> 5952 (sps overlays)
#define SM_SPS  SM_W1                     // 512 floats (epilogue only)
#define SM_B1   5952                      // 112 floats -> 6400
#define SM_AHI  6464                      // 67*288 = 19296 (row 66 = zeros)
#define SMEM_TOTAL (SM_AHI + 19296)       // 25760

__device__ __forceinline__ void mma_f16(float* d, const uint32_t* a, const uint32_t* b) {
    asm volatile("mma.sync.aligned.m16n8k16.row.col.f32.f16.f16.f32 "
                 "{%0,%1,%2,%3}, {%4,%5,%6,%7}, {%8,%9}, {%0,%1,%2,%3};"
                 : "+f"(d[0]), "+f"(d[1]), "+f"(d[2]), "+f"(d[3])
                 : "r"(a[0]), "r"(a[1]), "r"(a[2]), "r"(a[3]), "r"(b[0]), "r"(b[1]));
}

// ---------------------------------------------------------------------------
// Prep: w2 [224,112,3] -> fp16 fragment order [kk][jgrp][ks][lane][8B]
// ---------------------------------------------------------------------------
__global__ void prep_b_kernel(const float* __restrict__ w2) {
    int t = blockIdx.x * blockDim.x + threadIdx.x;
    if (t >= 3 * C2 * C1) return;
    int half = t & 1;
    int slot = (t >> 1) & 1;
    int lane = (t >> 2) & 31;
    int ks   = (t >> 7) % 7;
    int jgrp = (t / 896) % 28;
    int kk   = t / 25088;
    int g = lane >> 2, tig = lane & 3;
    int o = jgrp * 8 + g;
    int c = ks * 16 + slot * 8 + tig * 2 + half;
    g_bf[t] = __float2half(w2[o * (C1 * 3) + c * 3 + kk]);
}

// ---------------------------------------------------------------------------
// Fused kernel: resample+PE (warp/polyline) -> conv1 (channel-stationary) ->
// fp16 mma GEMM (B via __ldg from L1, barrier-free mainloop) -> LN -> store.
// 256 threads = 8 warps (2wm x 4wn; warp tile 32x56). TILE_M=64, occ 2.
// ---------------------------------------------------------------------------
__global__ __launch_bounds__(256, 2)
void fused_mma_kernel(const float* __restrict__ geoms,
                      const int* __restrict__ lengths,
                      const float* __restrict__ w1,
                      const float* __restrict__ b1,
                      const float* __restrict__ b2,
                      const float* __restrict__ gamma,
                      const float* __restrict__ beta,
                      float* __restrict__ out_geo,
                      float* __restrict__ out_coords) {
    __shared__ __align__(128) char smem[SMEM_TOTAL];
    int tid = threadIdx.x;
    int wid = tid >> 5;
    int lane = tid & 31;
    int tile_base = blockIdx.x * TILE_M;
    int poly_base = (tile_base == 0) ? 0 : (tile_base - 1) / 5;

    float* sbg = (float*)(smem + SM_BGB);
    float* sc  = (float*)(smem + SM_SC);
    float* sw1 = (float*)(smem + SM_W1);
    float* sb1 = (float*)(smem + SM_B1);
    float* sps = (float*)(smem + SM_SPS);

    for (int t = tid; t < 672; t += 256) sw1[t] = w1[t];
    if (tid < C1) sb1[tid] = b1[tid];
    if (tid < C2) {
        sbg[tid]          = b2[tid];
        sbg[C2 + tid]     = gamma[tid];
        sbg[2 * C2 + tid] = beta[tid];
    }

    // ---- fused resample + PE: warp per polyline, 2 passes over 8 warps ----
    const float PI = 3.14159265358979323846f;
    #pragma unroll
    for (int pass = 0; pass < 2; pass++) {
        int r = wid + pass * 8;              // 0..15, need 0..13
        int pol = poly_base + r;
        if (r < 14 && pol < KPOLY) {
            const float2* gp = (const float2*)(geoms + (size_t)pol * (PMAX * 2));
            float2 pt = make_float2(0.f, 0.f);
            if (lane < PMAX) pt = gp[lane];
            int L = lengths[pol];

            float nx = __shfl_down_sync(0xffffffffu, pt.x, 1);
            float ny = __shfl_down_sync(0xffffffffu, pt.y, 1);
            float dx = nx - pt.x;
            float dy = ny - pt.y;
            float sq = dx * dx + dy * dy;
            float sl = (sq > 0.f) ? sqrtf(sq) : 0.f;
            if (lane >= L - 1 || lane >= PMAX - 1) sl = 0.f;

            float incl = sl;
            #pragma unroll
            for (int off = 1; off < 32; off <<= 1) {
                float v = __shfl_up_sync(0xffffffffu, incl, off);
                if (lane >= off) incl += v;
            }
            float cum = __shfl_up_sync(0xffffffffu, incl, 1);
            if (lane == 0) cum = 0.f;

            float total = __shfl_sync(0xffffffffu, cum, PMAX - 1);
            bool degen = (total < 1e-6f);
            float p0x = __shfl_sync(0xffffffffu, pt.x, 0);
            float p0y = __shfl_sync(0xffffffffu, pt.y, 0);

            int grp = lane >> 3;
            int f = lane & 7;
            float fr = (float)(1 << f) * PI;

            #pragma unroll
            for (int j = 0; j < NUM_PTS; j++) {
                float target = 0.25f * (float)j * total;
                unsigned m = __ballot_sync(0xffffffffu, cum >= target) & 0x3FFFFFFFu;
                int idx = m ? (__ffs(m) - 1) : (PMAX - 1);
                int hi = L - 1;
                idx = idx < 1 ? 1 : (idx > hi ? hi : idx);

                float cumm1 = __shfl_sync(0xffffffffu, cum, idx - 1);
                float segm1 = __shfl_sync(0xffffffffu, sl, idx - 1);
                float px0   = __shfl_sync(0xffffffffu, pt.x, idx - 1);
                float py0   = __shfl_sync(0xffffffffu, pt.y, idx - 1);
                float dx0   = __shfl_sync(0xffffffffu, dx, idx - 1);
                float dy0   = __shfl_sync(0xffffffffu, dy, idx - 1);

                float t = (target - cumm1) / (segm1 + 1e-8f);
                float px = px0 + t * dx0;
                float py = py0 + t * dy0;
                if (degen) { px = p0x; py = p0y; }

                float ncx = (px + 30.f) * (1.f / 60.f);
                float ncy = (py + 15.f) * (1.f / 30.f);

                if (lane == 0) {
                    sc[r * 10 + j * 2 + 0] = ncx;
                    sc[r * 10 + j * 2 + 1] = ncy;
                    out_coords[(size_t)pol * 10 + j * 2 + 0] = ncx;
                    out_coords[(size_t)pol * 10 + j * 2 + 1] = ncy;
                }
                float cv = (grp < 2) ? ncx : ncy;
                float sv, cvs;
                sincosf(cv * fr, &sv, &cvs);
                float val = (grp & 1) ? cvs : sv;
                out_geo[(size_t)pol * (NUM_PTS * GEO_DIM) + (size_t)j * GEO_DIM + lane] = val;
            }
        }
    }
    __syncthreads();   // sc + sw1 + sb1 ready

    // ---- channel-stationary A build (fragment-paired layout, stride 288) ----
    if (tid < 2 * C1) {
        int tc = (tid < C1) ? tid : (tid - C1);
        int th = (tid < C1) ? 0 : 1;
        float wr[6], br;
        #pragma unroll
        for (int k = 0; k < 6; k++) wr[k] = sw1[tc * 6 + k];
        br = sb1[tc];
        int ksc = tc >> 4, r16 = tc & 15;
        int slot = r16 >> 3, tg = (r16 & 7) >> 1, half = r16 & 1;
        int coff = ksc * 32 + tg * 8 + slot * 4 + half * 2;

        for (int i = th; i < 67; i += 2) {
            float h = 0.f;
            int R = tile_base + i - 1;
            if (i < 66 && R >= 0 && R < ROWS_TOTAL) {
                int poly = R / 5;
                int p = R - poly * 5;
                const float* scp = sc + (poly - poly_base) * 10;
                float a1 = br;
                #pragma unroll
                for (int k3 = 0; k3 < 3; k3++) {
                    int q = p + k3 - 1;
                    if (q >= 0 && q < NUM_PTS)
                        a1 += wr[k3] * scp[q * 2] + wr[3 + k3] * scp[q * 2 + 1];
                }
                h = fmaxf(a1, 0.f);
            }
            *(__half*)(smem + SM_AHI + i * SAB_A + coff) = __float2half(h);
        }
    }
    __syncthreads();   // A ready; no more barriers until epilogue

    int wm = wid >> 2;           // 0..1
    int wn = wid & 3;            // 0..3
    int rbase = wm * 32;
    int n0 = wn * 56;
    int g = lane >> 2;
    int tig = lane & 3;
    int tb5 = tile_base % 5;
    // per-warp B base in fragment-ordered global (uint2 units)
    const uint2* bwarp = (const uint2*)g_bf + wn * (7 * 224) + lane;

    float acc[2][7][4];
    #pragma unroll
    for (int mi = 0; mi < 2; mi++)
        #pragma unroll
        for (int j = 0; j < 7; j++)
            #pragma unroll
            for (int q = 0; q < 4; q++) acc[mi][j][q] = 0.f;

    // ---- 3 phases x 7 k-steps, barrier-free; B from L1 via __ldg ----
    #pragma unroll
    for (int kk = 0; kk < 3; kk++) {
        uint32_t abase[2][2];
        #pragma unroll
        for (int mi = 0; mi < 2; mi++) {
            #pragma unroll
            for (int h = 0; h < 2; h++) {
                int r = rbase + mi * 16 + g + 8 * h;
                int p = (tb5 + r) % 5;
                int tap = p + kk - 1;
                bool valid = (tap >= 0) && (tap < NUM_PTS);
                int er = valid ? (r + kk) : 66;
                abase[mi][h] = (uint32_t)er * SAB_A + (uint32_t)(tig * 8);
            }
        }

        #pragma unroll
        for (int ks = 0; ks < KSTEPS; ks++) {
            uint32_t a[2][4];
            #pragma unroll
            for (int mi = 0; mi < 2; mi++) {
                uint2 v0 = *(const uint2*)(smem + SM_AHI + abase[mi][0] + ks * 32);
                uint2 v1 = *(const uint2*)(smem + SM_AHI + abase[mi][1] + ks * 32);
                a[mi][0] = v0.x; a[mi][1] = v1.x; a[mi][2] = v0.y; a[mi][3] = v1.y;
            }
            #pragma unroll
            for (int j = 0; j < 7; j++) {
                uint2 bv = __ldg(bwarp + kk * 6272 + j * 224 + ks * 32);
                uint32_t b[2] = {bv.x, bv.y};
                mma_f16(acc[0][j], a[0], b);
                mma_f16(acc[1][j], a[1], b);
            }
        }
    }

    // ---- epilogue: bias + relu, LN partials, reduce, store ----
    float s[2][2], s2[2][2];
    #pragma unroll
    for (int mi = 0; mi < 2; mi++)
        #pragma unroll
        for (int h = 0; h < 2; h++) { s[mi][h] = 0.f; s2[mi][h] = 0.f; }

    #pragma unroll
    for (int mi = 0; mi < 2; mi++) {
        #pragma unroll
        for (int j = 0; j < 7; j++) {
            int col = n0 + 8 * j + 2 * tig;
            float b0 = sbg[col], b1v = sbg[col + 1];
            #pragma unroll
            for (int q = 0; q < 4; q++) {
                float v = fmaxf(acc[mi][j][q] + ((q & 1) ? b1v : b0), 0.f);
                acc[mi][j][q] = v;
                int h = q >> 1;
                s[mi][h] += v;
                s2[mi][h] += v * v;
            }
        }
    }
    #pragma unroll
    for (int mi = 0; mi < 2; mi++)
        #pragma unroll
        for (int h = 0; h < 2; h++) {
            s[mi][h]  += __shfl_xor_sync(0xffffffffu, s[mi][h], 1);
            s[mi][h]  += __shfl_xor_sync(0xffffffffu, s[mi][h], 2);
            s2[mi][h] += __shfl_xor_sync(0xffffffffu, s2[mi][h], 1);
            s2[mi][h] += __shfl_xor_sync(0xffffffffu, s2[mi][h], 2);
        }
    __syncthreads();   // sw1 dead; sps overlay safe
    if (tig == 0) {
        #pragma unroll
        for (int mi = 0; mi < 2; mi++)
            #pragma unroll
            for (int h = 0; h < 2; h++) {
                int row = rbase + mi * 16 + g + 8 * h;
                sps[row * 4 + wn] = s[mi][h];
                sps[256 + row * 4 + wn] = s2[mi][h];
            }
    }
    __syncthreads();

    #pragma unroll
    for (int mi = 0; mi < 2; mi++) {
        #pragma unroll
        for (int h = 0; h < 2; h++) {
            int row = rbase + mi * 16 + g + 8 * h;
            float st  = sps[row * 4] + sps[row * 4 + 1] + sps[row * 4 + 2] + sps[row * 4 + 3];
            float st2 = sps[256 + row * 4] + sps[256 + row * 4 + 1]
                      + sps[256 + row * 4 + 2] + sps[256 + row * 4 + 3];
            float mu = st * (1.f / (float)C2);
            float rs = rsqrtf(st2 * (1.f / (float)C2) - mu * mu + 1e-5f);
            int grow = tile_base + row;
            if (grow < ROWS_TOTAL) {
                float* op = out_geo + (size_t)grow * GEO_DIM + PE_DIM;
                #pragma unroll
                for (int j = 0; j < 7; j++) {
                    int col = n0 + 8 * j + 2 * tig;
                    float v0 = (acc[mi][j][2 * h + 0] - mu) * rs * sbg[C2 + col] + sbg[2 * C2 + col];
                    float v1 = (acc[mi][j][2 * h + 1] - mu) * rs * sbg[C2 + col + 1] + sbg[2 * C2 + col + 1];
                    *(float2*)(op + col) = make_float2(v0, v1);
                }
            }
        }
    }
}

// ---------------------------------------------------------------------------
extern "C" void kernel_launch(void* const* d_in, const int* in_sizes, int n_in,
                              void* d_out, int out_size) {
    const float* geoms   = (const float*)d_in[0];
    const int*   lengths = (const int*)d_in[1];
    const float* w1      = (const float*)d_in[2];
    const float* b1      = (const float*)d_in[3];
    const float* w2      = (const float*)d_in[4];
    const float* b2      = (const float*)d_in[5];
    const float* gamma   = (const float*)d_in[6];
    const float* beta    = (const float*)d_in[7];

    float* out_geo    = (float*)d_out;                                     // [K,5,256]
    float* out_coords = (float*)d_out + (size_t)KPOLY * NUM_PTS * GEO_DIM; // [K,5,2]

    (void)in_sizes; (void)n_in; (void)out_size;

    {
        int n = 3 * C2 * C1;
        prep_b_kernel<<<(n + 255) / 256, 256>>>(w2);
    }
    fused_mma_kernel<<<GRID_C, 256>>>(geoms, lengths, w1, b1, b2, gamma, beta,
                                      out_geo, out_coords);
}

// round 16
// speedup vs baseline: 1.4214x; 1.4214x over previous
#include <cuda_runtime.h>
#include <cuda_fp16.h>
#include <math.h>
#include <stdint.h>

#define KPOLY 20000
#define PMAX 30
#define NUM_PTS 5
#define C1 112
#define C2 224
#define PE_DIM 32
#define GEO_DIM 256
#define ROWS_TOTAL (KPOLY * NUM_PTS)   // 100000
#define TILE_M 64
#define GRID_C ((ROWS_TOTAL + TILE_M - 1) / TILE_M)   // 1563
#define KSTEPS 7

// B fragment-ordered global, chunked:
// [kk][half][jgrp][ksl][lane][8B]; half0: ks 0-3 (28672 B), half1: ks 4-6 (21504 B)
#define BKK_BYTES 50176
#define BCH0_BYTES 28672
#define BCH1_BYTES 21504
__device__ __half g_bf[3 * BKK_BYTES / 2];

// SMEM layout (bytes); total 85248 -> 2 CTAs/SM
#define SAB_A 288                         // A row stride (LDS.64 conflict-free)
#define SM_SPS  0                         // 512 floats = 2048
#define SM_BGB  2048                      // 672 floats -> 4736
#define SM_SC   4736                      // 160 floats -> 5376
#define SM_W1   5376                      // 672 floats -> 8064
#define SM_B1   8064                      // 112 floats -> 8512
#define SM_AHI  8576                      // 67*288 = 19296 -> 27872 (row 66 = zeros)
#define SM_B0   27904                     // chunk buffer 0: 28672 -> 56576
#define SM_B1B  56576                     // chunk buffer 1: 28672 -> 85248
#define SMEM_TOTAL 85248

__device__ __forceinline__ uint32_t smem_u32(const void* p) {
    uint32_t a;
    asm("{ .reg .u64 t; cvta.to.shared.u64 t, %1; cvt.u32.u64 %0, t; }" : "=r"(a) : "l"(p));
    return a;
}
__device__ __forceinline__ void cp_async16(uint32_t dst, const void* src) {
    asm volatile("cp.async.ca.shared.global [%0], [%1], 16;" :: "r"(dst), "l"(src));
}
__device__ __forceinline__ void mma_f16(float* d, const uint32_t* a, const uint32_t* b) {
    asm volatile("mma.sync.aligned.m16n8k16.row.col.f32.f16.f16.f32 "
                 "{%0,%1,%2,%3}, {%4,%5,%6,%7}, {%8,%9}, {%0,%1,%2,%3};"
                 : "+f"(d[0]), "+f"(d[1]), "+f"(d[2]), "+f"(d[3])
                 : "r"(a[0]), "r"(a[1]), "r"(a[2]), "r"(a[3]), "r"(b[0]), "r"(b[1]));
}

// ---------------------------------------------------------------------------
// Kernel 1 (merged): blocks [0,2500): resample+PE; rest: w2 -> chunked frag order
// ---------------------------------------------------------------------------
#define RESAMPLE_BLOCKS 2500
#define PREP_BLOCKS 294

__global__ __launch_bounds__(256)
void resample_prep_kernel(const float* __restrict__ geoms,
                          const int* __restrict__ lengths,
                          const float* __restrict__ w2,
                          float* __restrict__ out_geo,
                          float* __restrict__ out_coords) {
    if (blockIdx.x >= RESAMPLE_BLOCKS) {
        int t = (blockIdx.x - RESAMPLE_BLOCKS) * blockDim.x + threadIdx.x;
        if (t < 3 * C2 * C1) {
            int half = t & 1;
            int slot = (t >> 1) & 1;
            int lane = (t >> 2) & 31;
            int u = t >> 7;                 // 0..587
            int kk = u / 196;
            int v = u - kk * 196;
            int jgrp, ks;
            if (v < 112) { jgrp = v >> 2; ks = v & 3; }
            else { int w = v - 112; jgrp = w / 3; ks = 4 + (w - (w / 3) * 3); }
            int g = lane >> 2, tig = lane & 3;
            int o = jgrp * 8 + g;
            int c = ks * 16 + slot * 8 + tig * 2 + half;
            g_bf[t] = __float2half(w2[o * (C1 * 3) + c * 3 + kk]);
        }
        return;
    }

    int warp = (blockIdx.x * blockDim.x + threadIdx.x) >> 5;
    int lane = threadIdx.x & 31;
    if (warp >= KPOLY) return;

    const float2* g = (const float2*)(geoms + (size_t)warp * (PMAX * 2));
    float2 pt = make_float2(0.f, 0.f);
    if (lane < PMAX) pt = g[lane];
    int L = lengths[warp];

    float nx = __shfl_down_sync(0xffffffffu, pt.x, 1);
    float ny = __shfl_down_sync(0xffffffffu, pt.y, 1);
    float dx = nx - pt.x;
    float dy = ny - pt.y;
    float sq = dx * dx + dy * dy;
    float s = (sq > 0.f) ? sqrtf(sq) : 0.f;
    if (lane >= L - 1 || lane >= PMAX - 1) s = 0.f;

    float incl = s;
    #pragma unroll
    for (int off = 1; off < 32; off <<= 1) {
        float v = __shfl_up_sync(0xffffffffu, incl, off);
        if (lane >= off) incl += v;
    }
    float cum = __shfl_up_sync(0xffffffffu, incl, 1);
    if (lane == 0) cum = 0.f;

    float total = __shfl_sync(0xffffffffu, cum, PMAX - 1);
    bool degen = (total < 1e-6f);
    float p0x = __shfl_sync(0xffffffffu, pt.x, 0);
    float p0y = __shfl_sync(0xffffffffu, pt.y, 0);

    const float PI = 3.14159265358979323846f;
    int grp = lane >> 3;
    int f = lane & 7;
    float fr = (float)(1 << f) * PI;

    #pragma unroll
    for (int j = 0; j < NUM_PTS; j++) {
        float target = 0.25f * (float)j * total;
        unsigned m = __ballot_sync(0xffffffffu, cum >= target) & 0x3FFFFFFFu;
        int idx = m ? (__ffs(m) - 1) : (PMAX - 1);
        int hi = L - 1;
        idx = idx < 1 ? 1 : (idx > hi ? hi : idx);

        float cumm1 = __shfl_sync(0xffffffffu, cum, idx - 1);
        float segm1 = __shfl_sync(0xffffffffu, s, idx - 1);
        float px0   = __shfl_sync(0xffffffffu, pt.x, idx - 1);
        float py0   = __shfl_sync(0xffffffffu, pt.y, idx - 1);
        float dx0   = __shfl_sync(0xffffffffu, dx, idx - 1);
        float dy0   = __shfl_sync(0xffffffffu, dy, idx - 1);

        float t = (target - cumm1) / (segm1 + 1e-8f);
        float px = px0 + t * dx0;
        float py = py0 + t * dy0;
        if (degen) { px = p0x; py = p0y; }

        float ncx = (px + 30.f) * (1.f / 60.f);
        float ncy = (py + 15.f) * (1.f / 30.f);

        if (lane == 0) {
            out_coords[(size_t)warp * (NUM_PTS * 2) + j * 2 + 0] = ncx;
            out_coords[(size_t)warp * (NUM_PTS * 2) + j * 2 + 1] = ncy;
        }
        float cv = (grp < 2) ? ncx : ncy;
        float sv, cvs;
        sincosf(cv * fr, &sv, &cvs);
        float val = (grp & 1) ? cvs : sv;
        out_geo[(size_t)warp * (NUM_PTS * GEO_DIM) + (size_t)j * GEO_DIM + lane] = val;
    }
}

// ---------------------------------------------------------------------------
// chunk MMA: NKS k-steps starting at KS0, B from given smem buffer
// ---------------------------------------------------------------------------
template<int NKS, int KS0>
__device__ __forceinline__ void mma_chunk(const char* smem, const char* bbuf,
                                          const uint32_t abase[2][2],
                                          int wn, int lane,
                                          float acc[2][7][4]) {
    const char* bbase = bbuf + wn * (7 * NKS * 256) + lane * 8;
    #pragma unroll
    for (int ksl = 0; ksl < NKS; ksl++) {
        const int ks = KS0 + ksl;
        uint32_t a[2][4];
        #pragma unroll
        for (int mi = 0; mi < 2; mi++) {
            uint2 v0 = *(const uint2*)(smem + SM_AHI + abase[mi][0] + ks * 32);
            uint2 v1 = *(const uint2*)(smem + SM_AHI + abase[mi][1] + ks * 32);
            a[mi][0] = v0.x; a[mi][1] = v1.x; a[mi][2] = v0.y; a[mi][3] = v1.y;
        }
        #pragma unroll
        for (int j = 0; j < 7; j++) {
            uint2 bv = *(const uint2*)(bbase + (j * NKS + ksl) * 256);
            uint32_t b[2] = {bv.x, bv.y};
            mma_f16(acc[0][j], a[0], b);
            mma_f16(acc[1][j], a[1], b);
        }
    }
}

// ---------------------------------------------------------------------------
// Kernel C: channel-stationary conv1 -> fp16 mma, 6-chunk double-buffered
// cp.async pipeline -> LN. 256 threads = 8 warps (2wm x 4wn). occ 2.
// ---------------------------------------------------------------------------
__global__ __launch_bounds__(256, 2)
void conv_mma_kernel(const float* __restrict__ coords,
                     const float* __restrict__ w1,
                     const float* __restrict__ b1,
                     const float* __restrict__ b2,
                     const float* __restrict__ gamma,
                     const float* __restrict__ beta,
                     float* __restrict__ out_geo) {
    extern __shared__ __align__(1024) char smem[];
    int tid = threadIdx.x;
    int wid = tid >> 5;
    int lane = tid & 31;
    int tile_base = blockIdx.x * TILE_M;
    int poly_base = (tile_base == 0) ? 0 : (tile_base - 1) / 5;

    float* sps = (float*)(smem + SM_SPS);
    float* sbg = (float*)(smem + SM_BGB);
    float* sc  = (float*)(smem + SM_SC);
    float* sw1 = (float*)(smem + SM_W1);
    float* sb1 = (float*)(smem + SM_B1);
    uint32_t sB[2] = { smem_u32(smem + SM_B0), smem_u32(smem + SM_B1B) };

    // issue chunks 0 and 1 immediately (overlap preamble + A build)
    #define ISSUE_CHUNK(c) do {                                                  \
        const int _kk = (c) >> 1, _hb = (c) & 1;                                 \
        const int _bytes = _hb ? BCH1_BYTES : BCH0_BYTES;                        \
        const char* _g = (const char*)g_bf + _kk * BKK_BYTES + _hb * BCH0_BYTES; \
        uint32_t _d = sB[(c) & 1];                                               \
        for (int _e = tid * 16; _e < _bytes; _e += 256 * 16)                     \
            cp_async16(_d + _e, _g + _e);                                        \
        asm volatile("cp.async.commit_group;" ::: "memory");                     \
    } while (0)

    ISSUE_CHUNK(0);
    ISSUE_CHUNK(1);

    for (int t = tid; t < 672; t += 256) sw1[t] = w1[t];
    if (tid < C1) sb1[tid] = b1[tid];
    if (tid < C2) {
        sbg[tid]          = b2[tid];
        sbg[C2 + tid]     = gamma[tid];
        sbg[2 * C2 + tid] = beta[tid];
    }
    if (tid < 160) {
        int pol = poly_base + tid / 10;
        sc[tid] = (pol < KPOLY) ? coords[(size_t)pol * 10 + (tid % 10)] : 0.f;
    }
    __syncthreads();

    // ---- channel-stationary A build (fragment-paired layout, stride 288) ----
    if (tid < 2 * C1) {
        int tc = (tid < C1) ? tid : (tid - C1);
        int th = (tid < C1) ? 0 : 1;
        float wr[6], br;
        #pragma unroll
        for (int k = 0; k < 6; k++) wr[k] = sw1[tc * 6 + k];
        br = sb1[tc];
        int ksc = tc >> 4, r16 = tc & 15;
        int slot = r16 >> 3, tg = (r16 & 7) >> 1, half = r16 & 1;
        int coff = ksc * 32 + tg * 8 + slot * 4 + half * 2;

        for (int i = th; i < 67; i += 2) {
            float h = 0.f;
            int R = tile_base + i - 1;
            if (i < 66 && R >= 0 && R < ROWS_TOTAL) {
                int poly = R / 5;
                int p = R - poly * 5;
                const float* scp = sc + (poly - poly_base) * 10;
                float a1 = br;
                #pragma unroll
                for (int k3 = 0; k3 < 3; k3++) {
                    int q = p + k3 - 1;
                    if (q >= 0 && q < NUM_PTS)
                        a1 += wr[k3] * scp[q * 2] + wr[3 + k3] * scp[q * 2 + 1];
                }
                h = fmaxf(a1, 0.f);
            }
            *(__half*)(smem + SM_AHI + i * SAB_A + coff) = __float2half(h);
        }
    }
    __syncthreads();   // A ready

    int wm = wid >> 2;
    int wn = wid & 3;
    int rbase = wm * 32;
    int n0 = wn * 56;
    int g = lane >> 2;
    int tig = lane & 3;
    int tb5 = tile_base % 5;

    float acc[2][7][4];
    #pragma unroll
    for (int mi = 0; mi < 2; mi++)
        #pragma unroll
        for (int j = 0; j < 7; j++)
            #pragma unroll
            for (int q = 0; q < 4; q++) acc[mi][j][q] = 0.f;

    // ---- 3 kk-phases x 2 half-chunks, double-buffered pipeline ----
    #pragma unroll
    for (int kk = 0; kk < 3; kk++) {
        uint32_t abase[2][2];
        #pragma unroll
        for (int mi = 0; mi < 2; mi++) {
            #pragma unroll
            for (int h = 0; h < 2; h++) {
                int r = rbase + mi * 16 + g + 8 * h;
                int p = (tb5 + r) % 5;
                int tap = p + kk - 1;
                bool valid = (tap >= 0) && (tap < NUM_PTS);
                int er = valid ? (r + kk) : 66;
                abase[mi][h] = (uint32_t)er * SAB_A + (uint32_t)(tig * 8);
            }
        }

        // chunk c0 = 2*kk (half 0: ks 0..3)
        {
            asm volatile("cp.async.wait_group 1;" ::: "memory");
            __syncthreads();
            const char* bbuf = smem + (((2 * kk) & 1) ? SM_B1B : SM_B0);
            mma_chunk<4, 0>(smem, bbuf, abase, wn, lane, acc);
            __syncthreads();
            if (2 * kk + 2 <= 5) ISSUE_CHUNK(2 * kk + 2);
        }
        // chunk c1 = 2*kk+1 (half 1: ks 4..6)
        {
            if (2 * kk + 1 == 5) {
                asm volatile("cp.async.wait_group 0;" ::: "memory");
            } else {
                asm volatile("cp.async.wait_group 1;" ::: "memory");
            }
            __syncthreads();
            const char* bbuf = smem + (((2 * kk + 1) & 1) ? SM_B1B : SM_B0);
            mma_chunk<3, 4>(smem, bbuf, abase, wn, lane, acc);
            __syncthreads();
            if (2 * kk + 3 <= 5) ISSUE_CHUNK(2 * kk + 3);
        }
    }
    #undef ISSUE_CHUNK

    // ---- epilogue: bias + relu, LN partials, reduce, store (verified) ----
    float s[2][2], s2[2][2];
    #pragma unroll
    for (int mi = 0; mi < 2; mi++)
        #pragma unroll
        for (int h = 0; h < 2; h++) { s[mi][h] = 0.f; s2[mi][h] = 0.f; }

    #pragma unroll
    for (int mi = 0; mi < 2; mi++) {
        #pragma unroll
        for (int j = 0; j < 7; j++) {
            int col = n0 + 8 * j + 2 * tig;
            float b0 = sbg[col], b1v = sbg[col + 1];
            #pragma unroll
            for (int q = 0; q < 4; q++) {
                float v = fmaxf(acc[mi][j][q] + ((q & 1) ? b1v : b0), 0.f);
                acc[mi][j][q] = v;
                int h = q >> 1;
                s[mi][h] += v;
                s2[mi][h] += v * v;
            }
        }
    }
    #pragma unroll
    for (int mi = 0; mi < 2; mi++)
        #pragma unroll
        for (int h = 0; h < 2; h++) {
            s[mi][h]  += __shfl_xor_sync(0xffffffffu, s[mi][h], 1);
            s[mi][h]  += __shfl_xor_sync(0xffffffffu, s[mi][h], 2);
            s2[mi][h] += __shfl_xor_sync(0xffffffffu, s2[mi][h], 1);
            s2[mi][h] += __shfl_xor_sync(0xffffffffu, s2[mi][h], 2);
        }
    if (tig == 0) {
        #pragma unroll
        for (int mi = 0; mi < 2; mi++)
            #pragma unroll
            for (int h = 0; h < 2; h++) {
                int row = rbase + mi * 16 + g + 8 * h;
                sps[row * 4 + wn] = s[mi][h];
                sps[256 + row * 4 + wn] = s2[mi][h];
            }
    }
    __syncthreads();

    #pragma unroll
    for (int mi = 0; mi < 2; mi++) {
        #pragma unroll
        for (int h = 0; h < 2; h++) {
            int row = rbase + mi * 16 + g + 8 * h;
            float st  = sps[row * 4] + sps[row * 4 + 1] + sps[row * 4 + 2] + sps[row * 4 + 3];
            float st2 = sps[256 + row * 4] + sps[256 + row * 4 + 1]
                      + sps[256 + row * 4 + 2] + sps[256 + row * 4 + 3];
            float mu = st * (1.f / (float)C2);
            float rs = rsqrtf(st2 * (1.f / (float)C2) - mu * mu + 1e-5f);
            int grow = tile_base + row;
            if (grow < ROWS_TOTAL) {
                float* op = out_geo + (size_t)grow * GEO_DIM + PE_DIM;
                #pragma unroll
                for (int j = 0; j < 7; j++) {
                    int col = n0 + 8 * j + 2 * tig;
                    float v0 = (acc[mi][j][2 * h + 0] - mu) * rs * sbg[C2 + col] + sbg[2 * C2 + col];
                    float v1 = (acc[mi][j][2 * h + 1] - mu) * rs * sbg[C2 + col + 1] + sbg[2 * C2 + col + 1];
                    *(float2*)(op + col) = make_float2(v0, v1);
                }
            }
        }
    }
}

// ---------------------------------------------------------------------------
extern "C" void kernel_launch(void* const* d_in, const int* in_sizes, int n_in,
                              void* d_out, int out_size) {
    const float* geoms   = (const float*)d_in[0];
    const int*   lengths = (const int*)d_in[1];
    const float* w1      = (const float*)d_in[2];
    const float* b1      = (const float*)d_in[3];
    const float* w2      = (const float*)d_in[4];
    const float* b2      = (const float*)d_in[5];
    const float* gamma   = (const float*)d_in[6];
    const float* beta    = (const float*)d_in[7];

    float* out_geo    = (float*)d_out;                                     // [K,5,256]
    float* out_coords = (float*)d_out + (size_t)KPOLY * NUM_PTS * GEO_DIM; // [K,5,2]

    (void)in_sizes; (void)n_in; (void)out_size;

    cudaFuncSetAttribute(conv_mma_kernel,
                         cudaFuncAttributeMaxDynamicSharedMemorySize, SMEM_TOTAL);

    resample_prep_kernel<<<RESAMPLE_BLOCKS + PREP_BLOCKS, 256>>>(
        geoms, lengths, w2, out_geo, out_coords);
    conv_mma_kernel<<<GRID_C, 256, SMEM_TOTAL>>>(out_coords, w1, b1, b2, gamma, beta, out_geo);
}